// round 2
// baseline (speedup 1.0000x reference)
#include <cuda_runtime.h>
#include <cuda_bf16.h>
#include <math.h>

#define EPS_ 1e-5f
#define CN 100000
#define CE 1600000

// ---------------- device scratch (allocation-free rule: __device__ globals) ----
__device__ float g_yz[(size_t)CN * 128];   // [N,128] = [y | z] per layer (reused)
__device__ float g_h [(size_t)CN * 64];    // h1, then reused for h2
__device__ int   g_deg[CN];
__device__ int   g_cur[CN];
__device__ int   g_off[CN + 1];
__device__ int   g_csr[CE];
__device__ float g_W1[128 * 128];          // [W1l | W1r]
__device__ float g_W2[64 * 128];           // [W2l | W2r]
__device__ float g_gsum[128 * 64];
__device__ int   g_gcnt[128];
__device__ float g_s1[64], g_t1[64], g_s2[64], g_t2[64];

// ---------------- f32x2 packed math helpers ----------------
__device__ __forceinline__ unsigned long long pack2(float x, float y) {
    unsigned long long r;
    asm("mov.b64 %0, {%1, %2};" : "=l"(r) : "f"(x), "f"(y));
    return r;
}
__device__ __forceinline__ void unpack2(unsigned long long v, float& x, float& y) {
    asm("mov.b64 {%0, %1}, %2;" : "=f"(x), "=f"(y) : "l"(v));
}
__device__ __forceinline__ unsigned long long fma2(unsigned long long a,
                                                   unsigned long long b,
                                                   unsigned long long c) {
    unsigned long long d;
    asm("fma.rn.f32x2 %0, %1, %2, %3;" : "=l"(d) : "l"(a), "l"(b), "l"(c));
    return d;
}

// ---------------- init: zero scratch, fuse weights, fold BN+bias ----------------
__global__ void k_init(const float* __restrict__ W1l, const float* __restrict__ W1r,
                       const float* __restrict__ W2l, const float* __restrict__ W2r,
                       const float* __restrict__ b1,
                       const float* __restrict__ g1, const float* __restrict__ bb1,
                       const float* __restrict__ m1, const float* __restrict__ v1,
                       const float* __restrict__ b2,
                       const float* __restrict__ g2, const float* __restrict__ bb2,
                       const float* __restrict__ m2, const float* __restrict__ v2,
                       int n) {
    int i = blockIdx.x * blockDim.x + threadIdx.x;
    if (i < n) g_deg[i] = 0;
    if (i < 128 * 128) {
        int k = i >> 7, j = i & 127;
        g_W1[i] = (j < 64) ? W1l[k * 64 + (i & 63)] : W1r[k * 64 + (i & 63)];
    }
    if (i < 64 * 128) {
        int k = i >> 7, j = i & 127;
        g_W2[i] = (j < 64) ? W2l[k * 64 + (i & 63)] : W2r[k * 64 + (i & 63)];
    }
    if (i < 128 * 64) g_gsum[i] = 0.f;
    if (i < 128) g_gcnt[i] = 0;
    if (i < 64) {
        float s = g1[i] * rsqrtf(v1[i] + EPS_);
        g_s1[i] = s;
        g_t1[i] = bb1[i] + (b1[i] - m1[i]) * s;
        float s2 = g2[i] * rsqrtf(v2[i] + EPS_);
        g_s2[i] = s2;
        g_t2[i] = bb2[i] + (b2[i] - m2[i]) * s2;
    }
}

// ---------------- degree histogram + graph node counts ----------------
__global__ void k_count(const int* __restrict__ dst, const int* __restrict__ batch,
                        int e, int n) {
    int i = blockIdx.x * blockDim.x + threadIdx.x;
    if (i < e) atomicAdd(&g_deg[dst[i]], 1);
    if (i < n) atomicAdd(&g_gcnt[batch[i]], 1);
}

// ---------------- single-block exclusive scan over deg -> off, cur ----------------
__global__ void k_scan(int n) {
    __shared__ int ssum[1024];
    int t = threadIdx.x;
    int per = (n + 1023) >> 10;
    int beg = t * per;
    int end = min(beg + per, n);
    int s = 0;
    for (int i = beg; i < end; i++) s += g_deg[i];
    ssum[t] = s;
    __syncthreads();
    for (int o = 1; o < 1024; o <<= 1) {
        int v = 0;
        if (t >= o) v = ssum[t - o];
        __syncthreads();
        ssum[t] += v;
        __syncthreads();
    }
    int run = ssum[t] - s;   // exclusive prefix of this chunk
    for (int i = beg; i < end; i++) {
        g_off[i] = run;
        g_cur[i] = run;
        run += g_deg[i];
    }
    if (t == 1023) g_off[n] = ssum[1023];
}

// ---------------- CSR scatter ----------------
__global__ void k_scatter(const int* __restrict__ src, const int* __restrict__ dst, int e) {
    int i = blockIdx.x * blockDim.x + threadIdx.x;
    if (i < e) {
        int d = dst[i];
        int pos = atomicAdd(&g_cur[d], 1);
        g_csr[pos] = src[i];
    }
}

// ---------------- GEMM: out[N,128] = X[N,K] @ W[K,128], packed f32x2 FMAs -------
template <int K>
__global__ __launch_bounds__(256) void k_gemm(const float* __restrict__ X,
                                              const float* __restrict__ W,
                                              float* __restrict__ out, int n) {
    __shared__ float Xs[32][68];     // transposed tile, padded (16B-aligned rows)
    __shared__ float Ws[32][128];
    const int t = threadIdx.x;
    const int lane = t & 31;
    const int w = t >> 5;
    const int c4 = lane * 4;
    const int r8 = w * 8;
    const int m0 = blockIdx.x * 64;

    unsigned long long acc[4][4];
#pragma unroll
    for (int i = 0; i < 4; i++)
#pragma unroll
        for (int j = 0; j < 4; j++) acc[i][j] = 0ull;

    for (int kb = 0; kb < K; kb += 32) {
#pragma unroll
        for (int l = 0; l < 8; l++) {        // X tile: 64 rows x 32 k
            int idx = t + l * 256;
            int row = idx >> 5;
            int kk = idx & 31;
            float v = 0.f;
            if (m0 + row < n) v = X[(size_t)(m0 + row) * K + kb + kk];
            Xs[kk][row] = v;
        }
#pragma unroll
        for (int l = 0; l < 16; l++) {       // W tile: 32 k x 128 cols
            int idx = t + l * 256;
            int kk = idx >> 7;
            int c = idx & 127;
            Ws[kk][c] = W[(size_t)(kb + kk) * 128 + c];
        }
        __syncthreads();
#pragma unroll
        for (int kk = 0; kk < 32; kk++) {
            ulonglong2 a01 = *(const ulonglong2*)&Xs[kk][r8];
            ulonglong2 a23 = *(const ulonglong2*)&Xs[kk][r8 + 4];
            float4 wv = *(const float4*)&Ws[kk][c4];
            unsigned long long b0 = pack2(wv.x, wv.x);
            unsigned long long b1v = pack2(wv.y, wv.y);
            unsigned long long b2v = pack2(wv.z, wv.z);
            unsigned long long b3v = pack2(wv.w, wv.w);
            unsigned long long a0 = a01.x, a1 = a01.y, a2 = a23.x, a3 = a23.y;
            acc[0][0] = fma2(a0, b0, acc[0][0]);
            acc[0][1] = fma2(a0, b1v, acc[0][1]);
            acc[0][2] = fma2(a0, b2v, acc[0][2]);
            acc[0][3] = fma2(a0, b3v, acc[0][3]);
            acc[1][0] = fma2(a1, b0, acc[1][0]);
            acc[1][1] = fma2(a1, b1v, acc[1][1]);
            acc[1][2] = fma2(a1, b2v, acc[1][2]);
            acc[1][3] = fma2(a1, b3v, acc[1][3]);
            acc[2][0] = fma2(a2, b0, acc[2][0]);
            acc[2][1] = fma2(a2, b1v, acc[2][1]);
            acc[2][2] = fma2(a2, b2v, acc[2][2]);
            acc[2][3] = fma2(a2, b3v, acc[2][3]);
            acc[3][0] = fma2(a3, b0, acc[3][0]);
            acc[3][1] = fma2(a3, b1v, acc[3][1]);
            acc[3][2] = fma2(a3, b2v, acc[3][2]);
            acc[3][3] = fma2(a3, b3v, acc[3][3]);
        }
        __syncthreads();
    }

#pragma unroll
    for (int rp = 0; rp < 4; rp++) {
        int row0 = m0 + r8 + rp * 2;
        float lo[4], hi[4];
#pragma unroll
        for (int cc = 0; cc < 4; cc++) unpack2(acc[rp][cc], lo[cc], hi[cc]);
        if (row0 < n) {
            float4 o = {lo[0], lo[1], lo[2], lo[3]};
            *(float4*)&out[(size_t)row0 * 128 + c4] = o;
        }
        if (row0 + 1 < n) {
            float4 o = {hi[0], hi[1], hi[2], hi[3]};
            *(float4*)&out[(size_t)(row0 + 1) * 128 + c4] = o;
        }
    }
}

// ---------------- aggregate (warp/node) + mean + z + folded BN + ReLU ----------
__global__ __launch_bounds__(256) void k_agg(const float* __restrict__ yz,
                                             const float* __restrict__ s,
                                             const float* __restrict__ tt,
                                             float* __restrict__ h, int n) {
    int warp = (blockIdx.x * blockDim.x + threadIdx.x) >> 5;
    int lane = threadIdx.x & 31;
    if (warp >= n) return;
    int beg = g_off[warp];
    int end = g_off[warp + 1];
    const int c = lane * 2;
    float a0 = 0.f, a1 = 0.f;
    for (int e = beg; e < end; e++) {
        int sn = g_csr[e];
        float2 v = *(const float2*)&yz[(size_t)sn * 128 + c];
        a0 += v.x;
        a1 += v.y;
    }
    int deg = end - beg;
    float inv = (deg > 0) ? (1.f / (float)deg) : 0.f;
    float2 z = *(const float2*)&yz[(size_t)warp * 128 + 64 + c];
    float p0 = fmaf(a0, inv, z.x);
    float p1 = fmaf(a1, inv, z.y);
    float o0 = fmaxf(fmaf(p0, s[c], tt[c]), 0.f);
    float o1 = fmaxf(fmaf(p1, s[c + 1], tt[c + 1]), 0.f);
    float2 o = {o0, o1};
    *(float2*)&h[(size_t)warp * 64 + c] = o;
}

// ---------------- global mean pool (batch is sorted; counts come from k_count) --
__global__ void k_pool(const float* __restrict__ h, const int* __restrict__ batch, int n) {
    const int c = threadIdx.x;                 // 0..63
    const int base = blockIdx.x * 256;
    const int lim = min(base + 256, n);
    float acc = 0.f;
    int curg = -1;
    for (int node = base; node < lim; node++) {
        int g = batch[node];
        if (g != curg) {
            if (curg >= 0) atomicAdd(&g_gsum[curg * 64 + c], acc);
            curg = g;
            acc = 0.f;
        }
        acc += h[(size_t)node * 64 + c];
    }
    if (curg >= 0) atomicAdd(&g_gsum[curg * 64 + c], acc);
}

// ---------------- classifier head + log_softmax (one block, thread/graph) -------
__global__ __launch_bounds__(128) void k_head(const float* __restrict__ Wc1,
                                              const float* __restrict__ bc1,
                                              const float* __restrict__ g3,
                                              const float* __restrict__ b3,
                                              const float* __restrict__ m3,
                                              const float* __restrict__ v3,
                                              const float* __restrict__ Wc2,
                                              const float* __restrict__ bc2,
                                              float* __restrict__ out) {
    __shared__ float W1s[64 * 64];
    __shared__ float W2s[64 * 10];
    __shared__ float s3[64], t3[64], b2s[10];
    int t = threadIdx.x;
    for (int i = t; i < 64 * 64; i += 128) W1s[i] = Wc1[i];
    for (int i = t; i < 64 * 10; i += 128) W2s[i] = Wc2[i];
    if (t < 64) {
        float s = g3[t] * rsqrtf(v3[t] + EPS_);
        s3[t] = s;
        t3[t] = b3[t] + (bc1[t] - m3[t]) * s;
    }
    if (t < 10) b2s[t] = bc2[t];
    __syncthreads();

    int cnt = g_gcnt[t];
    float inv = (cnt > 0) ? (1.f / (float)cnt) : 0.f;
    float gv[64];
#pragma unroll
    for (int k = 0; k < 64; k++) gv[k] = g_gsum[t * 64 + k] * inv;

    float lg[10];
#pragma unroll
    for (int o = 0; o < 10; o++) lg[o] = b2s[o];

    for (int j = 0; j < 64; j++) {
        float d = 0.f;
#pragma unroll
        for (int k = 0; k < 64; k++) d = fmaf(gv[k], W1s[k * 64 + j], d);
        float hj = fmaxf(fmaf(d, s3[j], t3[j]), 0.f);
#pragma unroll
        for (int o = 0; o < 10; o++) lg[o] = fmaf(hj, W2s[j * 10 + o], lg[o]);
    }
    float mx = lg[0];
#pragma unroll
    for (int o = 1; o < 10; o++) mx = fmaxf(mx, lg[o]);
    float se = 0.f;
#pragma unroll
    for (int o = 0; o < 10; o++) se += expf(lg[o] - mx);
    float lse = logf(se);
#pragma unroll
    for (int o = 0; o < 10; o++) out[t * 10 + o] = lg[o] - mx - lse;
}

// ---------------- launch ----------------
extern "C" void kernel_launch(void* const* d_in, const int* in_sizes, int n_in,
                              void* d_out, int out_size) {
    const float* x      = (const float*)d_in[0];
    const int*   ei     = (const int*)d_in[1];
    const int*   batch  = (const int*)d_in[2];
    const float* W1l    = (const float*)d_in[3];
    const float* W1r    = (const float*)d_in[4];
    const float* b1     = (const float*)d_in[5];
    const float* W2l    = (const float*)d_in[6];
    const float* W2r    = (const float*)d_in[7];
    const float* b2     = (const float*)d_in[8];
    const float* bn1g   = (const float*)d_in[9];
    const float* bn1b   = (const float*)d_in[10];
    const float* bn1m   = (const float*)d_in[11];
    const float* bn1v   = (const float*)d_in[12];
    const float* bn2g   = (const float*)d_in[13];
    const float* bn2b   = (const float*)d_in[14];
    const float* bn2m   = (const float*)d_in[15];
    const float* bn2v   = (const float*)d_in[16];
    const float* bn3g   = (const float*)d_in[17];
    const float* bn3b   = (const float*)d_in[18];
    const float* bn3m   = (const float*)d_in[19];
    const float* bn3v   = (const float*)d_in[20];
    const float* Wc1    = (const float*)d_in[21];
    const float* bc1    = (const float*)d_in[22];
    const float* Wc2    = (const float*)d_in[23];
    const float* bc2    = (const float*)d_in[24];
    float* out = (float*)d_out;

    int n = in_sizes[0] / 128;
    int e = in_sizes[1] / 2;
    if (n > CN) n = CN;
    if (e > CE) e = CE;
    const int* src = ei;
    const int* dst = ei + e;

    int gi = (n + 255) / 256;
    k_init<<<gi, 256>>>(W1l, W1r, W2l, W2r,
                        b1, bn1g, bn1b, bn1m, bn1v,
                        b2, bn2g, bn2b, bn2m, bn2v, n);

    int ge = (e + 255) / 256;
    k_count<<<ge, 256>>>(dst, batch, e, n);
    k_scan<<<1, 1024>>>(n);
    k_scatter<<<ge, 256>>>(src, dst, e);

    int gb = (n + 63) / 64;
    int ga = (n + 7) / 8;

    {
        float* yz;  cudaGetSymbolAddress((void**)&yz, g_yz);
        float* h;   cudaGetSymbolAddress((void**)&h, g_h);
        float* w1;  cudaGetSymbolAddress((void**)&w1, g_W1);
        float* w2;  cudaGetSymbolAddress((void**)&w2, g_W2);
        float* s1;  cudaGetSymbolAddress((void**)&s1, g_s1);
        float* t1;  cudaGetSymbolAddress((void**)&t1, g_t1);
        float* s2;  cudaGetSymbolAddress((void**)&s2, g_s2);
        float* t2;  cudaGetSymbolAddress((void**)&t2, g_t2);

        k_gemm<128><<<gb, 256>>>(x, w1, yz, n);
        k_agg<<<ga, 256>>>(yz, s1, t1, h, n);
        k_gemm<64><<<gb, 256>>>(h, w2, yz, n);
        k_agg<<<ga, 256>>>(yz, s2, t2, h, n);

        int gp = (n + 255) / 256;
        k_pool<<<gp, 64>>>(h, batch, n);
    }

    k_head<<<1, 128>>>(Wc1, bc1, bn3g, bn3b, bn3m, bn3v, Wc2, bc2, out);
}

// round 3
// speedup vs baseline: 1.4092x; 1.4092x over previous
#include <cuda_runtime.h>
#include <cuda_bf16.h>
#include <math.h>

#define EPS_ 1e-5f
#define CN 100000
#define CE 1600000
#define SCAN_CHUNK 512          // elements per scan block
#define SCAN_NB ((CN + SCAN_CHUNK - 1) / SCAN_CHUNK)

// ---------------- device scratch ----------------
__device__ float g_yz[(size_t)CN * 128];
__device__ float g_h [(size_t)CN * 64];
__device__ int   g_deg[CN + 1024];       // padded for vector-load overshoot
__device__ int   g_cur[CN + 1024];
__device__ int   g_off[CN + 1024];
__device__ int   g_csr[CE];
__device__ int   g_part[1024];           // scan partials
__device__ float g_W1[128 * 128];
__device__ float g_W2[64 * 128];
__device__ float g_gsum[128 * 64];
__device__ int   g_gcnt[128];
__device__ float g_s1[64], g_t1[64], g_s2[64], g_t2[64];

// ---------------- f32x2 helpers ----------------
__device__ __forceinline__ unsigned long long pack2(float x, float y) {
    unsigned long long r;
    asm("mov.b64 %0, {%1, %2};" : "=l"(r) : "f"(x), "f"(y));
    return r;
}
__device__ __forceinline__ void unpack2(unsigned long long v, float& x, float& y) {
    asm("mov.b64 {%0, %1}, %2;" : "=f"(x), "=f"(y) : "l"(v));
}
__device__ __forceinline__ unsigned long long fma2(unsigned long long a,
                                                   unsigned long long b,
                                                   unsigned long long c) {
    unsigned long long d;
    asm("fma.rn.f32x2 %0, %1, %2, %3;" : "=l"(d) : "l"(a), "l"(b), "l"(c));
    return d;
}

// ---------------- init ----------------
__global__ void k_init(const float* __restrict__ W1l, const float* __restrict__ W1r,
                       const float* __restrict__ W2l, const float* __restrict__ W2r,
                       const float* __restrict__ b1,
                       const float* __restrict__ g1, const float* __restrict__ bb1,
                       const float* __restrict__ m1, const float* __restrict__ v1,
                       const float* __restrict__ b2,
                       const float* __restrict__ g2, const float* __restrict__ bb2,
                       const float* __restrict__ m2, const float* __restrict__ v2,
                       int n) {
    int i = blockIdx.x * blockDim.x + threadIdx.x;
    if (i < n) g_deg[i] = 0;
    if (i < 128 * 128) {
        int k = i >> 7, j = i & 127;
        g_W1[i] = (j < 64) ? W1l[k * 64 + (i & 63)] : W1r[k * 64 + (i & 63)];
    }
    if (i < 64 * 128) {
        int k = i >> 7, j = i & 127;
        g_W2[i] = (j < 64) ? W2l[k * 64 + (i & 63)] : W2r[k * 64 + (i & 63)];
    }
    if (i < 128 * 64) g_gsum[i] = 0.f;
    if (i < 128) g_gcnt[i] = 0;
    if (i < 64) {
        float s = g1[i] * rsqrtf(v1[i] + EPS_);
        g_s1[i] = s;
        g_t1[i] = bb1[i] + (b1[i] - m1[i]) * s;
        float s2 = g2[i] * rsqrtf(v2[i] + EPS_);
        g_s2[i] = s2;
        g_t2[i] = bb2[i] + (b2[i] - m2[i]) * s2;
    }
}

// ---------------- degree histogram + graph node counts (ILP 4) ----------------
__global__ void k_count(const int* __restrict__ dst, const int* __restrict__ batch,
                        int e, int n) {
    int base = blockIdx.x * blockDim.x * 4 + threadIdx.x;
    int d0 = -1, d1 = -1, d2 = -1, d3 = -1;
    if (base < e)                    d0 = dst[base];
    if (base + blockDim.x < e)       d1 = dst[base + blockDim.x];
    if (base + 2 * blockDim.x < e)   d2 = dst[base + 2 * blockDim.x];
    if (base + 3 * blockDim.x < e)   d3 = dst[base + 3 * blockDim.x];
    if (d0 >= 0) atomicAdd(&g_deg[d0], 1);
    if (d1 >= 0) atomicAdd(&g_deg[d1], 1);
    if (d2 >= 0) atomicAdd(&g_deg[d2], 1);
    if (d3 >= 0) atomicAdd(&g_deg[d3], 1);
    int bi = blockIdx.x * blockDim.x + threadIdx.x;
    if (bi < n) atomicAdd(&g_gcnt[batch[bi]], 1);
}

// ---------------- 3-phase scan ----------------
__global__ void k_scan1(int n, int nb) {      // per-block partial sums
    __shared__ int sh[256];
    int b = blockIdx.x;
    int t = threadIdx.x;
    int base = b * SCAN_CHUNK + t * 2;
    int s = 0;
    if (base < n)     s += g_deg[base];
    if (base + 1 < n) s += g_deg[base + 1];
    sh[t] = s;
    __syncthreads();
    for (int o = 128; o > 0; o >>= 1) {
        if (t < o) sh[t] += sh[t + o];
        __syncthreads();
    }
    if (t == 0) g_part[b] = sh[0];
}

__global__ void k_scan2(int n, int nb) {      // scan partials (1 block)
    __shared__ int sh[256];
    int t = threadIdx.x;
    int v = (t < nb) ? g_part[t] : 0;
    sh[t] = v;
    __syncthreads();
    for (int o = 1; o < 256; o <<= 1) {
        int u = (t >= o) ? sh[t - o] : 0;
        __syncthreads();
        sh[t] += u;
        __syncthreads();
    }
    g_part[t] = sh[t] - v;                    // exclusive
    if (t == 255) g_off[n] = sh[255];         // total edges
}

__global__ void k_scan3(int n, int nb) {      // write offsets + cursors
    __shared__ int sh[256];
    int b = blockIdx.x;
    int t = threadIdx.x;
    int base = b * SCAN_CHUNK + t * 2;
    int d0 = (base < n) ? g_deg[base] : 0;
    int d1 = (base + 1 < n) ? g_deg[base + 1] : 0;
    int s = d0 + d1;
    sh[t] = s;
    __syncthreads();
    for (int o = 1; o < 256; o <<= 1) {
        int u = (t >= o) ? sh[t - o] : 0;
        __syncthreads();
        sh[t] += u;
        __syncthreads();
    }
    int off0 = g_part[b] + sh[t] - s;
    if (base < n)     { g_off[base] = off0;          g_cur[base] = off0; }
    if (base + 1 < n) { g_off[base + 1] = off0 + d0; g_cur[base + 1] = off0 + d0; }
}

// ---------------- CSR scatter (ILP 4) ----------------
__global__ void k_scatter(const int* __restrict__ src, const int* __restrict__ dst, int e) {
    int base = blockIdx.x * blockDim.x * 4 + threadIdx.x;
#pragma unroll
    for (int u = 0; u < 4; u++) {
        int i = base + u * blockDim.x;
        if (i < e) {
            int d = dst[i];
            int sv = src[i];
            int pos = atomicAdd(&g_cur[d], 1);
            g_csr[pos] = sv;
        }
    }
}

// ---------------- GEMM: out[N,128] = X[N,K] @ W[K,128] ----------------
// 128x128 block tile, 256 threads: warp w -> rows w*16..w*16+15, lane -> cols lane*4
template <int K>
__global__ __launch_bounds__(256) void k_gemm(const float* __restrict__ X,
                                              const float* __restrict__ W,
                                              float* __restrict__ out, int n) {
    __shared__ float Xs[32][136];
    __shared__ float Ws[32][128];
    const int t = threadIdx.x;
    const int lane = t & 31;
    const int w = t >> 5;
    const int c4 = lane * 4;
    const int r16 = w * 16;
    const int m0 = blockIdx.x * 128;

    unsigned long long acc[8][4];
#pragma unroll
    for (int i = 0; i < 8; i++)
#pragma unroll
        for (int j = 0; j < 4; j++) acc[i][j] = 0ull;

    for (int kb = 0; kb < K; kb += 32) {
#pragma unroll
        for (int l = 0; l < 16; l++) {       // X tile: 128 rows x 32 k
            int idx = t + l * 256;
            int row = idx >> 5;
            int kk = idx & 31;
            float v = 0.f;
            if (m0 + row < n) v = X[(size_t)(m0 + row) * K + kb + kk];
            Xs[kk][row] = v;
        }
#pragma unroll
        for (int l = 0; l < 16; l++) {       // W tile: 32 k x 128 cols
            int idx = t + l * 256;
            int kk = idx >> 7;
            int c = idx & 127;
            Ws[kk][c] = W[(size_t)(kb + kk) * 128 + c];
        }
        __syncthreads();
#pragma unroll
        for (int kk = 0; kk < 32; kk++) {
            ulonglong2 a01 = *(const ulonglong2*)&Xs[kk][r16];
            ulonglong2 a23 = *(const ulonglong2*)&Xs[kk][r16 + 4];
            ulonglong2 a45 = *(const ulonglong2*)&Xs[kk][r16 + 8];
            ulonglong2 a67 = *(const ulonglong2*)&Xs[kk][r16 + 12];
            float4 wv = *(const float4*)&Ws[kk][c4];
            unsigned long long b0 = pack2(wv.x, wv.x);
            unsigned long long b1v = pack2(wv.y, wv.y);
            unsigned long long b2v = pack2(wv.z, wv.z);
            unsigned long long b3v = pack2(wv.w, wv.w);
            unsigned long long a[8] = {a01.x, a01.y, a23.x, a23.y,
                                       a45.x, a45.y, a67.x, a67.y};
#pragma unroll
            for (int r = 0; r < 8; r++) {
                acc[r][0] = fma2(a[r], b0, acc[r][0]);
                acc[r][1] = fma2(a[r], b1v, acc[r][1]);
                acc[r][2] = fma2(a[r], b2v, acc[r][2]);
                acc[r][3] = fma2(a[r], b3v, acc[r][3]);
            }
        }
        __syncthreads();
    }

#pragma unroll
    for (int rp = 0; rp < 8; rp++) {
        int row0 = m0 + r16 + rp * 2;
        float lo[4], hi[4];
#pragma unroll
        for (int cc = 0; cc < 4; cc++) unpack2(acc[rp][cc], lo[cc], hi[cc]);
        if (row0 < n) {
            float4 o = {lo[0], lo[1], lo[2], lo[3]};
            *(float4*)&out[(size_t)row0 * 128 + c4] = o;
        }
        if (row0 + 1 < n) {
            float4 o = {hi[0], hi[1], hi[2], hi[3]};
            *(float4*)&out[(size_t)(row0 + 1) * 128 + c4] = o;
        }
    }
}

// ---------------- aggregate (warp/node, 4-way edge unroll) ----------------
__global__ __launch_bounds__(256) void k_agg(const float* __restrict__ yz,
                                             const float* __restrict__ s,
                                             const float* __restrict__ tt,
                                             float* __restrict__ h, int n) {
    int warp = (blockIdx.x * blockDim.x + threadIdx.x) >> 5;
    int lane = threadIdx.x & 31;
    if (warp >= n) return;
    int beg = g_off[warp];
    int end = g_off[warp + 1];
    const int c = lane * 2;
    float a0 = 0.f, a1 = 0.f, b0 = 0.f, b1 = 0.f;
    float c0 = 0.f, c1 = 0.f, d0 = 0.f, d1 = 0.f;
    int e = beg;
    for (; e + 4 <= end; e += 4) {
        int s0 = g_csr[e], s1 = g_csr[e + 1], s2 = g_csr[e + 2], s3 = g_csr[e + 3];
        float2 v0 = *(const float2*)&yz[(size_t)s0 * 128 + c];
        float2 v1 = *(const float2*)&yz[(size_t)s1 * 128 + c];
        float2 v2 = *(const float2*)&yz[(size_t)s2 * 128 + c];
        float2 v3 = *(const float2*)&yz[(size_t)s3 * 128 + c];
        a0 += v0.x; a1 += v0.y;
        b0 += v1.x; b1 += v1.y;
        c0 += v2.x; c1 += v2.y;
        d0 += v3.x; d1 += v3.y;
    }
    for (; e < end; e++) {
        int sn = g_csr[e];
        float2 v = *(const float2*)&yz[(size_t)sn * 128 + c];
        a0 += v.x; a1 += v.y;
    }
    a0 += b0 + c0 + d0;
    a1 += b1 + c1 + d1;
    int deg = end - beg;
    float inv = (deg > 0) ? (1.f / (float)deg) : 0.f;
    float2 z = *(const float2*)&yz[(size_t)warp * 128 + 64 + c];
    float p0 = fmaf(a0, inv, z.x);
    float p1 = fmaf(a1, inv, z.y);
    float o0 = fmaxf(fmaf(p0, s[c], tt[c]), 0.f);
    float o1 = fmaxf(fmaf(p1, s[c + 1], tt[c + 1]), 0.f);
    float2 o = {o0, o1};
    *(float2*)&h[(size_t)warp * 64 + c] = o;
}

// ---------------- global mean pool (batch sorted; counts from k_count) ----------
__global__ void k_pool(const float* __restrict__ h, const int* __restrict__ batch, int n) {
    const int c = threadIdx.x;                 // 0..63
    const int base = blockIdx.x * 256;
    const int lim = min(base + 256, n);
    float acc = 0.f;
    int curg = -1;
    for (int node = base; node < lim; node++) {
        int g = batch[node];
        if (g != curg) {
            if (curg >= 0) atomicAdd(&g_gsum[curg * 64 + c], acc);
            curg = g;
            acc = 0.f;
        }
        acc += h[(size_t)node * 64 + c];
    }
    if (curg >= 0) atomicAdd(&g_gsum[curg * 64 + c], acc);
}

// ---------------- classifier head + log_softmax ----------------
__global__ __launch_bounds__(128) void k_head(const float* __restrict__ Wc1,
                                              const float* __restrict__ bc1,
                                              const float* __restrict__ g3,
                                              const float* __restrict__ b3,
                                              const float* __restrict__ m3,
                                              const float* __restrict__ v3,
                                              const float* __restrict__ Wc2,
                                              const float* __restrict__ bc2,
                                              float* __restrict__ out) {
    __shared__ float W1s[64 * 64];
    __shared__ float W2s[64 * 10];
    __shared__ float s3[64], t3[64], b2s[10];
    int t = threadIdx.x;
    for (int i = t; i < 64 * 64; i += 128) W1s[i] = Wc1[i];
    for (int i = t; i < 64 * 10; i += 128) W2s[i] = Wc2[i];
    if (t < 64) {
        float s = g3[t] * rsqrtf(v3[t] + EPS_);
        s3[t] = s;
        t3[t] = b3[t] + (bc1[t] - m3[t]) * s;
    }
    if (t < 10) b2s[t] = bc2[t];
    __syncthreads();

    int cnt = g_gcnt[t];
    float inv = (cnt > 0) ? (1.f / (float)cnt) : 0.f;
    float gv[64];
#pragma unroll
    for (int k = 0; k < 64; k++) gv[k] = g_gsum[t * 64 + k] * inv;

    float lg[10];
#pragma unroll
    for (int o = 0; o < 10; o++) lg[o] = b2s[o];

    for (int j = 0; j < 64; j++) {
        float d = 0.f;
#pragma unroll
        for (int k = 0; k < 64; k++) d = fmaf(gv[k], W1s[k * 64 + j], d);
        float hj = fmaxf(fmaf(d, s3[j], t3[j]), 0.f);
#pragma unroll
        for (int o = 0; o < 10; o++) lg[o] = fmaf(hj, W2s[j * 10 + o], lg[o]);
    }
    float mx = lg[0];
#pragma unroll
    for (int o = 1; o < 10; o++) mx = fmaxf(mx, lg[o]);
    float se = 0.f;
#pragma unroll
    for (int o = 0; o < 10; o++) se += expf(lg[o] - mx);
    float lse = logf(se);
#pragma unroll
    for (int o = 0; o < 10; o++) out[t * 10 + o] = lg[o] - mx - lse;
}

// ---------------- launch ----------------
extern "C" void kernel_launch(void* const* d_in, const int* in_sizes, int n_in,
                              void* d_out, int out_size) {
    const float* x      = (const float*)d_in[0];
    const int*   ei     = (const int*)d_in[1];
    const int*   batch  = (const int*)d_in[2];
    const float* W1l    = (const float*)d_in[3];
    const float* W1r    = (const float*)d_in[4];
    const float* b1     = (const float*)d_in[5];
    const float* W2l    = (const float*)d_in[6];
    const float* W2r    = (const float*)d_in[7];
    const float* b2     = (const float*)d_in[8];
    const float* bn1g   = (const float*)d_in[9];
    const float* bn1b   = (const float*)d_in[10];
    const float* bn1m   = (const float*)d_in[11];
    const float* bn1v   = (const float*)d_in[12];
    const float* bn2g   = (const float*)d_in[13];
    const float* bn2b   = (const float*)d_in[14];
    const float* bn2m   = (const float*)d_in[15];
    const float* bn2v   = (const float*)d_in[16];
    const float* bn3g   = (const float*)d_in[17];
    const float* bn3b   = (const float*)d_in[18];
    const float* bn3m   = (const float*)d_in[19];
    const float* bn3v   = (const float*)d_in[20];
    const float* Wc1    = (const float*)d_in[21];
    const float* bc1    = (const float*)d_in[22];
    const float* Wc2    = (const float*)d_in[23];
    const float* bc2    = (const float*)d_in[24];
    float* out = (float*)d_out;

    int n = in_sizes[0] / 128;
    int e = in_sizes[1] / 2;
    if (n > CN) n = CN;
    if (e > CE) e = CE;
    const int* src = ei;
    const int* dst = ei + e;

    int gi = (n + 255) / 256;
    k_init<<<gi, 256>>>(W1l, W1r, W2l, W2r,
                        b1, bn1g, bn1b, bn1m, bn1v,
                        b2, bn2g, bn2b, bn2m, bn2v, n);

    int ge4 = (e + 1023) / 1024;
    k_count<<<ge4, 256>>>(dst, batch, e, n);

    int nb = (n + SCAN_CHUNK - 1) / SCAN_CHUNK;
    k_scan1<<<nb, 256>>>(n, nb);
    k_scan2<<<1, 256>>>(n, nb);
    k_scan3<<<nb, 256>>>(n, nb);

    k_scatter<<<ge4, 256>>>(src, dst, e);

    int gb = (n + 127) / 128;
    int ga = (n + 7) / 8;

    {
        float* yz;  cudaGetSymbolAddress((void**)&yz, g_yz);
        float* h;   cudaGetSymbolAddress((void**)&h, g_h);
        float* w1;  cudaGetSymbolAddress((void**)&w1, g_W1);
        float* w2;  cudaGetSymbolAddress((void**)&w2, g_W2);
        float* s1;  cudaGetSymbolAddress((void**)&s1, g_s1);
        float* t1;  cudaGetSymbolAddress((void**)&t1, g_t1);
        float* s2;  cudaGetSymbolAddress((void**)&s2, g_s2);
        float* t2;  cudaGetSymbolAddress((void**)&t2, g_t2);

        k_gemm<128><<<gb, 256>>>(x, w1, yz, n);
        k_agg<<<ga, 256>>>(yz, s1, t1, h, n);
        k_gemm<64><<<gb, 256>>>(h, w2, yz, n);
        k_agg<<<ga, 256>>>(yz, s2, t2, h, n);

        int gp = (n + 255) / 256;
        k_pool<<<gp, 64>>>(h, batch, n);
    }

    k_head<<<1, 128>>>(Wc1, bc1, bn3g, bn3b, bn3m, bn3v, Wc2, bc2, out);
}

// round 4
// speedup vs baseline: 1.4302x; 1.0149x over previous
#include <cuda_runtime.h>
#include <cuda_bf16.h>
#include <cuda_fp16.h>
#include <math.h>

#define EPS_ 1e-5f
#define CN 100000
#define CE 1600000
#define SCAN_CHUNK 512
#define SCAN_NB ((CN + SCAN_CHUNK - 1) / SCAN_CHUNK)

// ---------------- device scratch ----------------
__device__ __half g_y[(size_t)CN * 64];    // aggregated-side GEMM output (fp16)
__device__ float  g_z[(size_t)CN * 64];    // self-side GEMM output (fp32)
__device__ float  g_h[(size_t)CN * 64];    // post-BN/ReLU node features
__device__ int    g_deg[CN + 1024];
__device__ int    g_cur[CN + 1024];
__device__ int    g_off[CN + 1024];
__device__ int    g_csr[CE];
__device__ int    g_part[1024];
__device__ float  g_W1[128 * 128];
__device__ float  g_W2[64 * 128];
__device__ float  g_gsum[128 * 64];
__device__ int    g_gcnt[128];
__device__ float  g_s1[64], g_t1[64], g_s2[64], g_t2[64];

// ---------------- f32x2 helpers ----------------
__device__ __forceinline__ unsigned long long pack2(float x, float y) {
    unsigned long long r;
    asm("mov.b64 %0, {%1, %2};" : "=l"(r) : "f"(x), "f"(y));
    return r;
}
__device__ __forceinline__ void unpack2(unsigned long long v, float& x, float& y) {
    asm("mov.b64 {%0, %1}, %2;" : "=f"(x), "=f"(y) : "l"(v));
}
__device__ __forceinline__ unsigned long long fma2(unsigned long long a,
                                                   unsigned long long b,
                                                   unsigned long long c) {
    unsigned long long d;
    asm("fma.rn.f32x2 %0, %1, %2, %3;" : "=l"(d) : "l"(a), "l"(b), "l"(c));
    return d;
}

// ---------------- init ----------------
__global__ void k_init(const float* __restrict__ W1l, const float* __restrict__ W1r,
                       const float* __restrict__ W2l, const float* __restrict__ W2r,
                       const float* __restrict__ b1,
                       const float* __restrict__ g1, const float* __restrict__ bb1,
                       const float* __restrict__ m1, const float* __restrict__ v1,
                       const float* __restrict__ b2,
                       const float* __restrict__ g2, const float* __restrict__ bb2,
                       const float* __restrict__ m2, const float* __restrict__ v2,
                       int n) {
    int i = blockIdx.x * blockDim.x + threadIdx.x;
    if (i < n) g_deg[i] = 0;
    if (i < 128 * 128) {
        int k = i >> 7, j = i & 127;
        g_W1[i] = (j < 64) ? W1l[k * 64 + (i & 63)] : W1r[k * 64 + (i & 63)];
    }
    if (i < 64 * 128) {
        int k = i >> 7, j = i & 127;
        g_W2[i] = (j < 64) ? W2l[k * 64 + (i & 63)] : W2r[k * 64 + (i & 63)];
    }
    if (i < 128 * 64) g_gsum[i] = 0.f;
    if (i < 128) g_gcnt[i] = 0;
    if (i < 64) {
        float s = g1[i] * rsqrtf(v1[i] + EPS_);
        g_s1[i] = s;
        g_t1[i] = bb1[i] + (b1[i] - m1[i]) * s;
        float s2 = g2[i] * rsqrtf(v2[i] + EPS_);
        g_s2[i] = s2;
        g_t2[i] = bb2[i] + (b2[i] - m2[i]) * s2;
    }
}

// ---------------- degree histogram + graph node counts (ILP 4) ----------------
__global__ void k_count(const int* __restrict__ dst, const int* __restrict__ batch,
                        int e, int n) {
    int base = blockIdx.x * blockDim.x * 4 + threadIdx.x;
    int d0 = -1, d1 = -1, d2 = -1, d3 = -1;
    if (base < e)                    d0 = dst[base];
    if (base + blockDim.x < e)       d1 = dst[base + blockDim.x];
    if (base + 2 * blockDim.x < e)   d2 = dst[base + 2 * blockDim.x];
    if (base + 3 * blockDim.x < e)   d3 = dst[base + 3 * blockDim.x];
    if (d0 >= 0) atomicAdd(&g_deg[d0], 1);
    if (d1 >= 0) atomicAdd(&g_deg[d1], 1);
    if (d2 >= 0) atomicAdd(&g_deg[d2], 1);
    if (d3 >= 0) atomicAdd(&g_deg[d3], 1);
    int bi = blockIdx.x * blockDim.x + threadIdx.x;
    if (bi < n) atomicAdd(&g_gcnt[batch[bi]], 1);
}

// ---------------- 3-phase scan ----------------
__global__ void k_scan1(int n, int nb) {
    __shared__ int sh[256];
    int b = blockIdx.x;
    int t = threadIdx.x;
    int base = b * SCAN_CHUNK + t * 2;
    int s = 0;
    if (base < n)     s += g_deg[base];
    if (base + 1 < n) s += g_deg[base + 1];
    sh[t] = s;
    __syncthreads();
    for (int o = 128; o > 0; o >>= 1) {
        if (t < o) sh[t] += sh[t + o];
        __syncthreads();
    }
    if (t == 0) g_part[b] = sh[0];
}

__global__ void k_scan2(int n, int nb) {
    __shared__ int sh[256];
    int t = threadIdx.x;
    int v = (t < nb) ? g_part[t] : 0;
    sh[t] = v;
    __syncthreads();
    for (int o = 1; o < 256; o <<= 1) {
        int u = (t >= o) ? sh[t - o] : 0;
        __syncthreads();
        sh[t] += u;
        __syncthreads();
    }
    g_part[t] = sh[t] - v;
    if (t == 255) g_off[n] = sh[255];
}

__global__ void k_scan3(int n, int nb) {
    __shared__ int sh[256];
    int b = blockIdx.x;
    int t = threadIdx.x;
    int base = b * SCAN_CHUNK + t * 2;
    int d0 = (base < n) ? g_deg[base] : 0;
    int d1 = (base + 1 < n) ? g_deg[base + 1] : 0;
    int s = d0 + d1;
    sh[t] = s;
    __syncthreads();
    for (int o = 1; o < 256; o <<= 1) {
        int u = (t >= o) ? sh[t - o] : 0;
        __syncthreads();
        sh[t] += u;
        __syncthreads();
    }
    int off0 = g_part[b] + sh[t] - s;
    if (base < n)     { g_off[base] = off0;          g_cur[base] = off0; }
    if (base + 1 < n) { g_off[base + 1] = off0 + d0; g_cur[base + 1] = off0 + d0; }
}

// ---------------- CSR scatter (ILP 4) ----------------
__global__ void k_scatter(const int* __restrict__ src, const int* __restrict__ dst, int e) {
    int base = blockIdx.x * blockDim.x * 4 + threadIdx.x;
#pragma unroll
    for (int u = 0; u < 4; u++) {
        int i = base + u * blockDim.x;
        if (i < e) {
            int d = dst[i];
            int sv = src[i];
            int pos = atomicAdd(&g_cur[d], 1);
            g_csr[pos] = sv;
        }
    }
}

// ---------------- GEMM: [y(fp16) | z(fp32)] = X[N,K] @ W[K,128] ----------------
template <int K>
__global__ __launch_bounds__(256) void k_gemm(const float* __restrict__ X,
                                              const float* __restrict__ W,
                                              __half* __restrict__ Y,
                                              float* __restrict__ Z, int n) {
    __shared__ float Xs[32][136];
    __shared__ float Ws[32][128];
    const int t = threadIdx.x;
    const int lane = t & 31;
    const int w = t >> 5;
    const int c4 = lane * 4;
    const int r16 = w * 16;
    const int m0 = blockIdx.x * 128;

    unsigned long long acc[8][4];
#pragma unroll
    for (int i = 0; i < 8; i++)
#pragma unroll
        for (int j = 0; j < 4; j++) acc[i][j] = 0ull;

    for (int kb = 0; kb < K; kb += 32) {
#pragma unroll
        for (int l = 0; l < 16; l++) {
            int idx = t + l * 256;
            int row = idx >> 5;
            int kk = idx & 31;
            float v = 0.f;
            if (m0 + row < n) v = X[(size_t)(m0 + row) * K + kb + kk];
            Xs[kk][row] = v;
        }
#pragma unroll
        for (int l = 0; l < 16; l++) {
            int idx = t + l * 256;
            int kk = idx >> 7;
            int c = idx & 127;
            Ws[kk][c] = W[(size_t)(kb + kk) * 128 + c];
        }
        __syncthreads();
#pragma unroll
        for (int kk = 0; kk < 32; kk++) {
            ulonglong2 a01 = *(const ulonglong2*)&Xs[kk][r16];
            ulonglong2 a23 = *(const ulonglong2*)&Xs[kk][r16 + 4];
            ulonglong2 a45 = *(const ulonglong2*)&Xs[kk][r16 + 8];
            ulonglong2 a67 = *(const ulonglong2*)&Xs[kk][r16 + 12];
            float4 wv = *(const float4*)&Ws[kk][c4];
            unsigned long long b0 = pack2(wv.x, wv.x);
            unsigned long long b1v = pack2(wv.y, wv.y);
            unsigned long long b2v = pack2(wv.z, wv.z);
            unsigned long long b3v = pack2(wv.w, wv.w);
            unsigned long long a[8] = {a01.x, a01.y, a23.x, a23.y,
                                       a45.x, a45.y, a67.x, a67.y};
#pragma unroll
            for (int r = 0; r < 8; r++) {
                acc[r][0] = fma2(a[r], b0, acc[r][0]);
                acc[r][1] = fma2(a[r], b1v, acc[r][1]);
                acc[r][2] = fma2(a[r], b2v, acc[r][2]);
                acc[r][3] = fma2(a[r], b3v, acc[r][3]);
            }
        }
        __syncthreads();
    }

    const bool isY = (c4 < 64);
    const int zc = c4 - 64;
#pragma unroll
    for (int rp = 0; rp < 8; rp++) {
        int row0 = m0 + r16 + rp * 2;
        float lo[4], hi[4];
#pragma unroll
        for (int cc = 0; cc < 4; cc++) unpack2(acc[rp][cc], lo[cc], hi[cc]);
        if (isY) {
            if (row0 < n) {
                __half2 p0 = __float22half2_rn(make_float2(lo[0], lo[1]));
                __half2 p1 = __float22half2_rn(make_float2(lo[2], lo[3]));
                uint2 pk = {*(unsigned*)&p0, *(unsigned*)&p1};
                *(uint2*)&Y[(size_t)row0 * 64 + c4] = pk;
            }
            if (row0 + 1 < n) {
                __half2 p0 = __float22half2_rn(make_float2(hi[0], hi[1]));
                __half2 p1 = __float22half2_rn(make_float2(hi[2], hi[3]));
                uint2 pk = {*(unsigned*)&p0, *(unsigned*)&p1};
                *(uint2*)&Y[(size_t)(row0 + 1) * 64 + c4] = pk;
            }
        } else {
            if (row0 < n) {
                float4 o = {lo[0], lo[1], lo[2], lo[3]};
                *(float4*)&Z[(size_t)row0 * 64 + zc] = o;
            }
            if (row0 + 1 < n) {
                float4 o = {hi[0], hi[1], hi[2], hi[3]};
                *(float4*)&Z[(size_t)(row0 + 1) * 64 + zc] = o;
            }
        }
    }
}

// ---------------- aggregate (warp/node, 8-way edge unroll, fp16 gathers) -------
__global__ __launch_bounds__(256) void k_agg(const __half* __restrict__ Y,
                                             const float* __restrict__ Z,
                                             const float* __restrict__ s,
                                             const float* __restrict__ tt,
                                             float* __restrict__ h, int n) {
    int warp = (blockIdx.x * blockDim.x + threadIdx.x) >> 5;
    int lane = threadIdx.x & 31;
    if (warp >= n) return;
    int beg = g_off[warp];
    int end = g_off[warp + 1];
    const int c = lane * 2;
    const __half2* Y2 = (const __half2*)Y;   // 32 half2 per row

    float a0 = 0.f, a1 = 0.f;
    int e = beg;
    for (; e + 8 <= end; e += 8) {
        int sn[8];
#pragma unroll
        for (int u = 0; u < 8; u++) sn[u] = g_csr[e + u];
        __half2 v[8];
#pragma unroll
        for (int u = 0; u < 8; u++) v[u] = Y2[(size_t)sn[u] * 32 + lane];
        float2 f0 = __half22float2(v[0]);
        float2 f1 = __half22float2(v[1]);
        float2 f2 = __half22float2(v[2]);
        float2 f3 = __half22float2(v[3]);
        float2 f4 = __half22float2(v[4]);
        float2 f5 = __half22float2(v[5]);
        float2 f6 = __half22float2(v[6]);
        float2 f7 = __half22float2(v[7]);
        a0 += ((f0.x + f1.x) + (f2.x + f3.x)) + ((f4.x + f5.x) + (f6.x + f7.x));
        a1 += ((f0.y + f1.y) + (f2.y + f3.y)) + ((f4.y + f5.y) + (f6.y + f7.y));
    }
    for (; e < end; e++) {
        int sn = g_csr[e];
        float2 f = __half22float2(Y2[(size_t)sn * 32 + lane]);
        a0 += f.x;
        a1 += f.y;
    }
    int deg = end - beg;
    float inv = (deg > 0) ? (1.f / (float)deg) : 0.f;
    float2 z = *(const float2*)&Z[(size_t)warp * 64 + c];
    float p0 = fmaf(a0, inv, z.x);
    float p1 = fmaf(a1, inv, z.y);
    float o0 = fmaxf(fmaf(p0, s[c], tt[c]), 0.f);
    float o1 = fmaxf(fmaf(p1, s[c + 1], tt[c + 1]), 0.f);
    float2 o = {o0, o1};
    *(float2*)&h[(size_t)warp * 64 + c] = o;
}

// ---------------- global mean pool ----------------
__global__ void k_pool(const float* __restrict__ h, const int* __restrict__ batch, int n) {
    const int c = threadIdx.x;
    const int base = blockIdx.x * 256;
    const int lim = min(base + 256, n);
    float acc = 0.f;
    int curg = -1;
    for (int node = base; node < lim; node++) {
        int g = batch[node];
        if (g != curg) {
            if (curg >= 0) atomicAdd(&g_gsum[curg * 64 + c], acc);
            curg = g;
            acc = 0.f;
        }
        acc += h[(size_t)node * 64 + c];
    }
    if (curg >= 0) atomicAdd(&g_gsum[curg * 64 + c], acc);
}

// ---------------- classifier head + log_softmax ----------------
__global__ __launch_bounds__(128) void k_head(const float* __restrict__ Wc1,
                                              const float* __restrict__ bc1,
                                              const float* __restrict__ g3,
                                              const float* __restrict__ b3,
                                              const float* __restrict__ m3,
                                              const float* __restrict__ v3,
                                              const float* __restrict__ Wc2,
                                              const float* __restrict__ bc2,
                                              float* __restrict__ out) {
    __shared__ float W1s[64 * 64];
    __shared__ float W2s[64 * 10];
    __shared__ float s3[64], t3[64], b2s[10];
    int t = threadIdx.x;
    for (int i = t; i < 64 * 64; i += 128) W1s[i] = Wc1[i];
    for (int i = t; i < 64 * 10; i += 128) W2s[i] = Wc2[i];
    if (t < 64) {
        float s = g3[t] * rsqrtf(v3[t] + EPS_);
        s3[t] = s;
        t3[t] = b3[t] + (bc1[t] - m3[t]) * s;
    }
    if (t < 10) b2s[t] = bc2[t];
    __syncthreads();

    int cnt = g_gcnt[t];
    float inv = (cnt > 0) ? (1.f / (float)cnt) : 0.f;
    float gv[64];
#pragma unroll
    for (int k = 0; k < 64; k++) gv[k] = g_gsum[t * 64 + k] * inv;

    float lg[10];
#pragma unroll
    for (int o = 0; o < 10; o++) lg[o] = b2s[o];

    for (int j = 0; j < 64; j++) {
        float d = 0.f;
#pragma unroll
        for (int k = 0; k < 64; k++) d = fmaf(gv[k], W1s[k * 64 + j], d);
        float hj = fmaxf(fmaf(d, s3[j], t3[j]), 0.f);
#pragma unroll
        for (int o = 0; o < 10; o++) lg[o] = fmaf(hj, W2s[j * 10 + o], lg[o]);
    }
    float mx = lg[0];
#pragma unroll
    for (int o = 1; o < 10; o++) mx = fmaxf(mx, lg[o]);
    float se = 0.f;
#pragma unroll
    for (int o = 0; o < 10; o++) se += expf(lg[o] - mx);
    float lse = logf(se);
#pragma unroll
    for (int o = 0; o < 10; o++) out[t * 10 + o] = lg[o] - mx - lse;
}

// ---------------- launch ----------------
extern "C" void kernel_launch(void* const* d_in, const int* in_sizes, int n_in,
                              void* d_out, int out_size) {
    const float* x      = (const float*)d_in[0];
    const int*   ei     = (const int*)d_in[1];
    const int*   batch  = (const int*)d_in[2];
    const float* W1l    = (const float*)d_in[3];
    const float* W1r    = (const float*)d_in[4];
    const float* b1     = (const float*)d_in[5];
    const float* W2l    = (const float*)d_in[6];
    const float* W2r    = (const float*)d_in[7];
    const float* b2     = (const float*)d_in[8];
    const float* bn1g   = (const float*)d_in[9];
    const float* bn1b   = (const float*)d_in[10];
    const float* bn1m   = (const float*)d_in[11];
    const float* bn1v   = (const float*)d_in[12];
    const float* bn2g   = (const float*)d_in[13];
    const float* bn2b   = (const float*)d_in[14];
    const float* bn2m   = (const float*)d_in[15];
    const float* bn2v   = (const float*)d_in[16];
    const float* bn3g   = (const float*)d_in[17];
    const float* bn3b   = (const float*)d_in[18];
    const float* bn3m   = (const float*)d_in[19];
    const float* bn3v   = (const float*)d_in[20];
    const float* Wc1    = (const float*)d_in[21];
    const float* bc1    = (const float*)d_in[22];
    const float* Wc2    = (const float*)d_in[23];
    const float* bc2    = (const float*)d_in[24];
    float* out = (float*)d_out;

    int n = in_sizes[0] / 128;
    int e = in_sizes[1] / 2;
    if (n > CN) n = CN;
    if (e > CE) e = CE;
    const int* src = ei;
    const int* dst = ei + e;

    int gi = (n + 255) / 256;
    k_init<<<gi, 256>>>(W1l, W1r, W2l, W2r,
                        b1, bn1g, bn1b, bn1m, bn1v,
                        b2, bn2g, bn2b, bn2m, bn2v, n);

    int ge4 = (e + 1023) / 1024;
    k_count<<<ge4, 256>>>(dst, batch, e, n);

    int nb = (n + SCAN_CHUNK - 1) / SCAN_CHUNK;
    k_scan1<<<nb, 256>>>(n, nb);
    k_scan2<<<1, 256>>>(n, nb);
    k_scan3<<<nb, 256>>>(n, nb);

    k_scatter<<<ge4, 256>>>(src, dst, e);

    int gb = (n + 127) / 128;
    int ga = (n + 7) / 8;

    {
        __half* y;  cudaGetSymbolAddress((void**)&y, g_y);
        float* z;   cudaGetSymbolAddress((void**)&z, g_z);
        float* h;   cudaGetSymbolAddress((void**)&h, g_h);
        float* w1;  cudaGetSymbolAddress((void**)&w1, g_W1);
        float* w2;  cudaGetSymbolAddress((void**)&w2, g_W2);
        float* s1;  cudaGetSymbolAddress((void**)&s1, g_s1);
        float* t1;  cudaGetSymbolAddress((void**)&t1, g_t1);
        float* s2;  cudaGetSymbolAddress((void**)&s2, g_s2);
        float* t2;  cudaGetSymbolAddress((void**)&t2, g_t2);

        k_gemm<128><<<gb, 256>>>(x, w1, y, z, n);
        k_agg<<<ga, 256>>>(y, z, s1, t1, h, n);
        k_gemm<64><<<gb, 256>>>(h, w2, y, z, n);
        k_agg<<<ga, 256>>>(y, z, s2, t2, h, n);

        int gp = (n + 255) / 256;
        k_pool<<<gp, 64>>>(h, batch, n);
    }

    k_head<<<1, 128>>>(Wc1, bc1, bn3g, bn3b, bn3m, bn3v, Wc2, bc2, out);
}